// round 8
// baseline (speedup 1.0000x reference)
#include <cuda_runtime.h>
#include <cuda_bf16.h>
#include <math.h>
#include <stdint.h>

#define BB 512
#define TT 64
#define HH 512
#define VV 780
#define N_AT 40
#define KC 4
#define MAX_NB 8
#define NMSG (BB*TT+1)
#define BT (BB*TT)
#define NSTOP (BT+BB)
#define H2 (2*HH)
#define NBLK 128

// k_scan dynamic smem: 3 weight slices [512][32] (swizzled) + 2 A chunk buffers [64][36]
#define AS 36
#define SMEM_SCAN ((3*512*32 + 2*64*AS) * 4)

// tgemm: 3-stage ring of (A[128][36] + B[32][132]) fp32 tiles
#define TG_ABUF (128*36)
#define TG_BBUF (32*132)
#define TG_STAGE (TG_ABUF + TG_BBUF)
#define SMEM_TG (3*TG_STAGE*4)

// ---------------- device scratch ----------------
__device__ float g_table [NMSG*HH];
__device__ float g_tableU[NMSG*HH];
__device__ float g_nodeZ [BB*N_AT*HH];
__device__ float g_nodeR [BB*N_AT*HH];
__device__ float g_nodeH [BB*N_AT*HH];
__device__ float g_xall  [BT*HH];
__device__ float g_rootx [BB*HH];
__device__ float g_Xz    [BT*HH];
__device__ float g_Xr    [BT*HH];
__device__ float g_Xh    [BT*HH];
__device__ float g_sumh  [BB*HH];
__device__ float g_sumg  [BB*HH];
__device__ float g_stopA [NSTOP*H2];
__device__ float g_predH [BT*HH];
__device__ float g_predS [BT*VV];
__device__ float g_score [NSTOP];
__device__ float g_red   [8];
__device__ unsigned g_bar;

__device__ __forceinline__ float sigf(float x){ return 1.f/(1.f+expf(-x)); }

__device__ __forceinline__ void cp_async16(uint32_t dst, const void* src){
    asm volatile("cp.async.cg.shared.global [%0], [%1], 16;\n" :: "r"(dst), "l"(src));
}
__device__ __forceinline__ void cp_async16z(uint32_t dst, const void* src, int bytes){
    asm volatile("cp.async.cg.shared.global [%0], [%1], 16, %2;\n" :: "r"(dst), "l"(src), "r"(bytes));
}
__device__ __forceinline__ void cp_commit(){ asm volatile("cp.async.commit_group;\n"); }
template<int N> __device__ __forceinline__ void cp_wait(){ asm volatile("cp.async.wait_group %0;\n" :: "n"(N)); }

__device__ __forceinline__ void mma_tf32(float* d, const uint32_t* a, const uint32_t* b){
    asm volatile(
        "mma.sync.aligned.m16n8k8.row.col.f32.tf32.tf32.f32 "
        "{%0,%1,%2,%3},{%4,%5,%6,%7},{%8,%9},{%0,%1,%2,%3};\n"
        : "+f"(d[0]), "+f"(d[1]), "+f"(d[2]), "+f"(d[3])
        : "r"(a[0]), "r"(a[1]), "r"(a[2]), "r"(a[3]), "r"(b[0]), "r"(b[1]));
}

// ---------------- x features ----------------
__global__ void k_xfeat(const float* __restrict__ node_rep,
                        const int* __restrict__ cidx,
                        const int* __restrict__ rcidx)
{
    int i = blockIdx.x; int c = threadIdx.x;
    if (i < BT) {
        int b = i / TT;
        const int* ci = cidx + (size_t)i*KC;
        float s0=0.f, s1=0.f;
        #pragma unroll
        for (int k=0;k<KC;k++){
            const float* nr = node_rep + ((size_t)b*N_AT + ci[k])*HH;
            s0 += nr[c]; s1 += nr[c+256];
        }
        g_xall[(size_t)i*HH + c]       = s0;
        g_xall[(size_t)i*HH + c + 256] = s1;
    } else {
        int b = i - BT;
        const int* ci = rcidx + (size_t)b*KC;
        float s0=0.f, s1=0.f;
        #pragma unroll
        for (int k=0;k<KC;k++){
            const float* nr = node_rep + ((size_t)b*N_AT + ci[k])*HH;
            s0 += nr[c]; s1 += nr[c+256];
        }
        g_rootx[b*HH + c]       = s0;
        g_rootx[b*HH + c + 256] = s1;
    }
}

// ---------------- gather node projections into per-(b,t) X arrays ----------------
__global__ void k_xproj(const int* __restrict__ cidx,
                        const float* __restrict__ bz,
                        const float* __restrict__ br,
                        const float* __restrict__ bh)
{
    int i = blockIdx.x;
    int b = i / TT;
    const int* ci = cidx + (size_t)i*KC;
    int r0 = b*N_AT;
    #pragma unroll
    for (int cc=0; cc<2; cc++){
        int c = threadIdx.x + cc*256;
        float sz = bz[c], sr = br[c], sh = bh[c];
        #pragma unroll
        for (int k=0;k<KC;k++){
            size_t row = (size_t)(r0 + ci[k])*HH + c;
            sz += g_nodeZ[row];
            sr += g_nodeR[row];
            sh += g_nodeH[row];
        }
        g_Xz[(size_t)i*HH + c] = sz;
        g_Xr[(size_t)i*HH + c] = sr;
        g_Xh[(size_t)i*HH + c] = sh;
    }
}

// ---------------- tf32 tensor-core GEMM ----------------
template<int EPI, bool NG, bool ZSEL>
__global__ void __launch_bounds__(256)
tgemm(const float* __restrict__ A, int lda,
      const float* __restrict__ Bm0, int ldb,
      const float* __restrict__ bias,
      float* __restrict__ C0, int ldc,
      int N, int K,
      const float* __restrict__ us,
      const float* Bm1, const float* Bm2,
      float* C1, float* C2)
{
    extern __shared__ float dynsm[];
    const int tid  = threadIdx.x;
    const int warp = tid >> 5, lane = tid & 31;
    const int wm = warp & 3, wn = warp >> 2;
    const int gid = lane >> 2, tig = lane & 3;
    const int by = blockIdx.y, bx = blockIdx.x;
    const int rowb = by*128, colb = bx*128;

    const float* Bm = Bm0;
    float* C = C0;
    if (ZSEL){
        if (blockIdx.z == 1){ Bm = Bm1; C = C1; }
        else if (blockIdx.z == 2){ Bm = Bm2; C = C2; }
    }

    const int aq0 = tid;
    const int bq0 = tid;

    uint32_t smem_base = (uint32_t)__cvta_generic_to_shared(dynsm);

    float acc[2][8][4];
    #pragma unroll
    for (int mt=0;mt<2;mt++)
        #pragma unroll
        for (int nt=0;nt<8;nt++)
            #pragma unroll
            for (int i=0;i<4;i++) acc[mt][nt][i]=0.f;

    const int nk = K >> 5;

    auto issue = [&](int kt, int stage){
        uint32_t sa = smem_base + stage*TG_STAGE*4;
        uint32_t sb = sa + TG_ABUF*4;
        #pragma unroll
        for (int i=0;i<4;i++){
            int q = aq0 + 256*i;
            int r = q >> 3, k4 = (q & 7)*4;
            cp_async16(sa + (r*36 + k4)*4, A + (size_t)(rowb + r)*lda + kt*32 + k4);
        }
        #pragma unroll
        for (int i=0;i<4;i++){
            int q = bq0 + 256*i;
            int kr = q >> 5, n4 = (q & 31)*4;
            uint32_t dst = sb + (kr*132 + n4)*4;
            if (NG){
                int col = colb + n4;
                int bytes = (col + 3 < N) ? 16 : ((col < N) ? (N - col)*4 : 0);
                const float* src = Bm + (size_t)(kt*32 + kr)*ldb + (bytes ? col : 0);
                cp_async16z(dst, src, bytes);
            } else {
                cp_async16(dst, Bm + (size_t)(kt*32 + kr)*ldb + colb + n4);
            }
        }
        cp_commit();
    };

    issue(0, 0);
    if (nk > 1) issue(1, 1);

    for (int it=0; it<nk; it++){
        if (it+2 < nk) issue(it+2, (it+2)%3);
        if (it+1 < nk) cp_wait<1>(); else cp_wait<0>();
        __syncthreads();

        const uint32_t* As = (const uint32_t*)(dynsm + (it%3)*TG_STAGE);
        const uint32_t* Bs = (const uint32_t*)(dynsm + (it%3)*TG_STAGE + TG_ABUF);

        #pragma unroll
        for (int ks=0; ks<4; ks++){
            uint32_t af[2][4];
            #pragma unroll
            for (int mt=0; mt<2; mt++){
                int r = wm*32 + mt*16 + gid;
                af[mt][0] = As[r*36 + ks*8 + tig];
                af[mt][1] = As[(r+8)*36 + ks*8 + tig];
                af[mt][2] = As[r*36 + ks*8 + tig + 4];
                af[mt][3] = As[(r+8)*36 + ks*8 + tig + 4];
            }
            uint32_t bf[8][2];
            #pragma unroll
            for (int nt=0; nt<8; nt++){
                int n = wn*64 + nt*8 + gid;
                bf[nt][0] = Bs[(ks*8 + tig)*132 + n];
                bf[nt][1] = Bs[(ks*8 + tig + 4)*132 + n];
            }
            #pragma unroll
            for (int mt=0; mt<2; mt++)
                #pragma unroll
                for (int nt=0; nt<8; nt++)
                    mma_tf32(acc[mt][nt], af[mt], bf[nt]);
        }
        __syncthreads();
    }

    if (EPI == 2){
        #pragma unroll
        for (int mt=0; mt<2; mt++){
            float s0 = 0.f, s1 = 0.f;
            #pragma unroll
            for (int nt=0; nt<8; nt++){
                int col = colb + wn*64 + nt*8 + 2*tig;
                float b0 = bias[col], b1 = bias[col+1];
                float u0 = us[col],  u1 = us[col+1];
                float v;
                v = acc[mt][nt][0] + b0; s0 += (v>0.f? v:0.f)*u0;
                v = acc[mt][nt][1] + b1; s0 += (v>0.f? v:0.f)*u1;
                v = acc[mt][nt][2] + b0; s1 += (v>0.f? v:0.f)*u0;
                v = acc[mt][nt][3] + b1; s1 += (v>0.f? v:0.f)*u1;
            }
            s0 += __shfl_xor_sync(0xffffffffu, s0, 1);
            s0 += __shfl_xor_sync(0xffffffffu, s0, 2);
            s1 += __shfl_xor_sync(0xffffffffu, s1, 1);
            s1 += __shfl_xor_sync(0xffffffffu, s1, 2);
            if (tig == 0){
                int row = rowb + wm*32 + mt*16 + gid;
                atomicAdd(&g_score[row], s0);
                atomicAdd(&g_score[row+8], s1);
            }
        }
    } else {
        #pragma unroll
        for (int mt=0; mt<2; mt++){
            #pragma unroll
            for (int nt=0; nt<8; nt++){
                int col = colb + wn*64 + nt*8 + 2*tig;
                int row = rowb + wm*32 + mt*16 + gid;
                #pragma unroll
                for (int i=0; i<4; i++){
                    int cc = col + (i & 1);
                    int rr = row + ((i >> 1) ? 8 : 0);
                    if (!NG || cc < N){
                        float v = acc[mt][nt][i];
                        if (EPI != 3) v += bias[cc];
                        if (EPI == 1) v = v > 0.f ? v : 0.f;
                        C[(size_t)rr*ldc + cc] = v;
                    }
                }
            }
        }
    }
}

// ---------------- persistent scan kernel: tf32 mma phases ----------------
// Grid barrier: per-thread release fence, block sync, thread 0 bumps counter
// and TIGHT-spins (no nanosleep: all 128 CTAs are co-resident at 1 CTA/SM, so
// forward progress is guaranteed and wakeup latency is one L2 round trip).
__device__ __forceinline__ void gsync(int& epoch)
{
    __threadfence();
    __syncthreads();
    if (threadIdx.x == 0){
        atomicAdd(&g_bar, 1u);
        unsigned tgt = (unsigned)epoch * NBLK;
        while (*((volatile unsigned*)&g_bar) < tgt) { }
    }
    epoch++;
    __syncthreads();
}

__global__ void __launch_bounds__(256, 1)
k_scan(const int* __restrict__ nei_h,
       const float* __restrict__ Wzh,
       const float* __restrict__ Whh,
       const float* __restrict__ Ur)
{
    extern __shared__ float smem[];
    float* Wz_s = smem;                    // [512][32] swizzled
    float* Wh_s = Wz_s + 512*32;
    float* Ur_s = Wh_s + 512*32;
    float* A_h  = Ur_s + 512*32;           // [64][AS]
    float* A_g  = A_h + 64*AS;

    const int tid = threadIdx.x;
    const int blk = blockIdx.x;
    const int rt = blk >> 4, ct = blk & 15;     // 8 row tiles x 16 col tiles
    const int r0 = rt*64, c0 = ct*32;
    const int warp = tid >> 5, lane = tid & 31;
    const int wm = warp & 3, wn = warp >> 2;    // warp tile 16x16
    const int gid = lane >> 2, tig = lane & 3;
    const int id4a = tid*2, id4b = tid*2+1;
    const int sra = id4a >> 3, ska = (id4a & 7)*4;
    const int srb = id4b >> 3, skb = (id4b & 7)*4;

    for (int idx = tid; idx < 512*32; idx += 256){
        int k = idx >> 5; int cc = idx & 31;
        int sw = cc ^ ((k & 3) << 3);
        Wz_s[k*32 + sw] = Wzh[(size_t)k*HH + c0 + cc];
        Wh_s[k*32 + sw] = Whh[(size_t)k*HH + c0 + cc];
        Ur_s[k*32 + sw] = Ur [(size_t)k*HH + c0 + cc];
    }
    __syncthreads();

    const uint32_t* Wz32 = (const uint32_t*)Wz_s;
    const uint32_t* Wh32 = (const uint32_t*)Wh_s;
    const uint32_t* Ur32 = (const uint32_t*)Ur_s;
    const uint32_t* Ah32 = (const uint32_t*)A_h;
    const uint32_t* Ag32 = (const uint32_t*)A_g;

    int epoch = 1;

    for (int t = 0; t < TT; t++){
        // ---- phase A: gather sum_h, sum_g ----
        #pragma unroll
        for (int rb=0; rb<4; rb++){
            int b = blk*4 + rb;
            const int* idx = nei_h + ((size_t)b*TT + t)*MAX_NB;
            int ii[8];
            #pragma unroll
            for (int n=0;n<8;n++) ii[n] = idx[n];
            #pragma unroll
            for (int cc=0; cc<2; cc++){
                int ch = tid + cc*256;
                float xr = g_Xr[((size_t)b*TT + t)*HH + ch];
                float ah=0.f, ag=0.f;
                #pragma unroll
                for (int n=0;n<8;n++){
                    size_t base = (size_t)ii[n]*HH + ch;
                    float hv = __ldcg(&g_table[base]);
                    float uv = __ldcg(&g_tableU[base]);
                    ah += hv;
                    ag += hv * sigf(xr + uv);
                }
                g_sumh[b*HH+ch] = ah;
                g_sumg[b*HH+ch] = ag;
            }
        }
        gsync(epoch);

        // ---- phase B: dual tf32 GEMM + GRU epilogue ----
        {
            float accz[2][4], acch[2][4];
            #pragma unroll
            for (int nt=0;nt<2;nt++)
                #pragma unroll
                for (int i=0;i<4;i++){ accz[nt][i]=0.f; acch[nt][i]=0.f; }

            float4 pha, phb, pga, pgb;
            pha = __ldcg((const float4*)&g_sumh[(size_t)(r0+sra)*HH + ska]);
            phb = __ldcg((const float4*)&g_sumh[(size_t)(r0+srb)*HH + skb]);
            pga = __ldcg((const float4*)&g_sumg[(size_t)(r0+sra)*HH + ska]);
            pgb = __ldcg((const float4*)&g_sumg[(size_t)(r0+srb)*HH + skb]);
            *(float4*)&A_h[sra*AS+ska] = pha; *(float4*)&A_h[srb*AS+skb] = phb;
            *(float4*)&A_g[sra*AS+ska] = pga; *(float4*)&A_g[srb*AS+skb] = pgb;
            __syncthreads();

            for (int chk=0; chk<16; chk++){
                if (chk < 15){
                    int k0 = (chk+1)*32;
                    pha = __ldcg((const float4*)&g_sumh[(size_t)(r0+sra)*HH + k0 + ska]);
                    phb = __ldcg((const float4*)&g_sumh[(size_t)(r0+srb)*HH + k0 + skb]);
                    pga = __ldcg((const float4*)&g_sumg[(size_t)(r0+sra)*HH + k0 + ska]);
                    pgb = __ldcg((const float4*)&g_sumg[(size_t)(r0+srb)*HH + k0 + skb]);
                }
                #pragma unroll
                for (int ks=0; ks<4; ks++){
                    int rb0 = wm*16 + gid;
                    uint32_t ah[4], ag[4];
                    ah[0]=Ah32[rb0*AS + ks*8 + tig];     ah[1]=Ah32[(rb0+8)*AS + ks*8 + tig];
                    ah[2]=Ah32[rb0*AS + ks*8 + tig + 4]; ah[3]=Ah32[(rb0+8)*AS + ks*8 + tig + 4];
                    ag[0]=Ag32[rb0*AS + ks*8 + tig];     ag[1]=Ag32[(rb0+8)*AS + ks*8 + tig];
                    ag[2]=Ag32[rb0*AS + ks*8 + tig + 4]; ag[3]=Ag32[(rb0+8)*AS + ks*8 + tig + 4];
                    int kg = chk*32 + ks*8;
                    #pragma unroll
                    for (int nt=0; nt<2; nt++){
                        int n = wn*16 + nt*8 + gid;
                        int nsw = n ^ (tig << 3);
                        uint32_t bz[2], bh[2];
                        bz[0] = Wz32[(kg+tig)*32 + nsw];
                        bz[1] = Wz32[(kg+tig+4)*32 + nsw];
                        bh[0] = Wh32[(kg+tig)*32 + nsw];
                        bh[1] = Wh32[(kg+tig+4)*32 + nsw];
                        mma_tf32(accz[nt], ah, bz);
                        mma_tf32(acch[nt], ag, bh);
                    }
                }
                __syncthreads();
                if (chk < 15){
                    *(float4*)&A_h[sra*AS+ska] = pha; *(float4*)&A_h[srb*AS+skb] = phb;
                    *(float4*)&A_g[sra*AS+ska] = pga; *(float4*)&A_g[srb*AS+skb] = pgb;
                    __syncthreads();
                }
            }

            #pragma unroll
            for (int nt=0; nt<2; nt++){
                #pragma unroll
                for (int half=0; half<2; half++){
                    int b   = r0 + wm*16 + gid + half*8;
                    int col = c0 + wn*16 + nt*8 + tig*2;
                    size_t xi = ((size_t)b*TT + t)*HH + col;
                    float2 xz = *(const float2*)&g_Xz[xi];
                    float2 xh = *(const float2*)&g_Xh[xi];
                    float2 sh = __ldcg((const float2*)&g_sumh[(size_t)b*HH + col]);
                    float z0 = sigf(xz.x + accz[nt][half*2+0]);
                    float z1 = sigf(xz.y + accz[nt][half*2+1]);
                    float p0 = tanhf(xh.x + acch[nt][half*2+0]);
                    float p1 = tanhf(xh.y + acch[nt][half*2+1]);
                    float2 out;
                    out.x = (1.f - z0)*sh.x + z0*p0;
                    out.y = (1.f - z1)*sh.y + z1*p1;
                    *(float2*)&g_table[((size_t)b*TT + t + 1)*HH + col] = out;
                }
            }
        }
        gsync(epoch);

        if (t == TT-1) break;

        // ---- phase C: tableU(new rows) = new_h @ Ur (tf32) ----
        {
            float accu[2][4];
            #pragma unroll
            for (int nt=0;nt<2;nt++)
                #pragma unroll
                for (int i=0;i<4;i++) accu[nt][i]=0.f;

            float4 pha, phb;
            pha = __ldcg((const float4*)&g_table[((size_t)(r0+sra)*TT + t + 1)*HH + ska]);
            phb = __ldcg((const float4*)&g_table[((size_t)(r0+srb)*TT + t + 1)*HH + skb]);
            *(float4*)&A_h[sra*AS+ska] = pha; *(float4*)&A_h[srb*AS+skb] = phb;
            __syncthreads();

            for (int chk=0; chk<16; chk++){
                if (chk < 15){
                    int k0 = (chk+1)*32;
                    pha = __ldcg((const float4*)&g_table[((size_t)(r0+sra)*TT + t + 1)*HH + k0 + ska]);
                    phb = __ldcg((const float4*)&g_table[((size_t)(r0+srb)*TT + t + 1)*HH + k0 + skb]);
                }
                #pragma unroll
                for (int ks=0; ks<4; ks++){
                    int rb0 = wm*16 + gid;
                    uint32_t ah[4];
                    ah[0]=Ah32[rb0*AS + ks*8 + tig];     ah[1]=Ah32[(rb0+8)*AS + ks*8 + tig];
                    ah[2]=Ah32[rb0*AS + ks*8 + tig + 4]; ah[3]=Ah32[(rb0+8)*AS + ks*8 + tig + 4];
                    int kg = chk*32 + ks*8;
                    #pragma unroll
                    for (int nt=0; nt<2; nt++){
                        int n = wn*16 + nt*8 + gid;
                        int nsw = n ^ (tig << 3);
                        uint32_t bu[2];
                        bu[0] = Ur32[(kg+tig)*32 + nsw];
                        bu[1] = Ur32[(kg+tig+4)*32 + nsw];
                        mma_tf32(accu[nt], ah, bu);
                    }
                }
                __syncthreads();
                if (chk < 15){
                    *(float4*)&A_h[sra*AS+ska] = pha; *(float4*)&A_h[srb*AS+skb] = phb;
                    __syncthreads();
                }
            }

            #pragma unroll
            for (int nt=0; nt<2; nt++){
                #pragma unroll
                for (int half=0; half<2; half++){
                    int b   = r0 + wm*16 + gid + half*8;
                    int col = c0 + wn*16 + nt*8 + tig*2;
                    float2 out;
                    out.x = accu[nt][half*2+0];
                    out.y = accu[nt][half*2+1];
                    *(float2*)&g_tableU[((size_t)b*TT + t + 1)*HH + col] = out;
                }
            }
        }
        gsync(epoch);
    }
}

// ---------------- deferred o gather + concat into stopA ----------------
__global__ void k_oall(const int* __restrict__ nei_o, const int* __restrict__ root_nei)
{
    int i = blockIdx.x;
    int c = blockIdx.y*256 + threadIdx.x;
    if (i < BT) {
        int tt = i % TT;
        float xv = g_xall[(size_t)i*HH + c];
        const int* idx = nei_o + (size_t)i*MAX_NB;
        float o = 0.f;
        #pragma unroll
        for (int n=0;n<MAX_NB;n++){
            int id = idx[n];
            if (id > 0 && ((id-1) % TT) < tt) o += g_table[(size_t)id*HH + c];
        }
        g_stopA[(size_t)i*H2 + c]      = xv;
        g_stopA[(size_t)i*H2 + HH + c] = o;
    } else {
        int b = i - BT;
        float xv = g_rootx[b*HH + c];
        const int* idx = root_nei + (size_t)b*MAX_NB;
        float o = 0.f;
        #pragma unroll
        for (int n=0;n<MAX_NB;n++) o += g_table[(size_t)idx[n]*HH + c];
        g_stopA[(size_t)i*H2 + c]      = xv;
        g_stopA[(size_t)i*H2 + HH + c] = o;
    }
}

// ---------------- stop loss / acc ----------------
__global__ void k_stoploss(const int* __restrict__ direction, const float* __restrict__ usb)
{
    int i = blockIdx.x*256 + threadIdx.x;
    float li = 0.f, ci = 0.f;
    if (i < NSTOP){
        float s = g_score[i] + usb[0];
        float tgt = (i < BT) ? (float)direction[i] : 0.f;
        float sp = (s > 0.f) ? (s + log1pf(expf(-s))) : log1pf(expf(s));
        li = sp - s*tgt;
        float pred = (s >= 0.f) ? 1.f : 0.f;
        ci = (pred == tgt) ? 1.f : 0.f;
    }
    __shared__ float rl[256], rc[256];
    rl[threadIdx.x]=li; rc[threadIdx.x]=ci;
    __syncthreads();
    for (int st=128; st>0; st>>=1){
        if (threadIdx.x < st){ rl[threadIdx.x]+=rl[threadIdx.x+st]; rc[threadIdx.x]+=rc[threadIdx.x+st]; }
        __syncthreads();
    }
    if (threadIdx.x==0){
        atomicAdd(&g_red[3], rl[0]);
        atomicAdd(&g_red[4], rc[0]);
    }
}

// ---------------- pred head CE / acc ----------------
__global__ void k_ce(const int* __restrict__ direction, const int* __restrict__ target)
{
    int i = blockIdx.x;
    int t = threadIdx.x;
    const float* S = g_predS + (size_t)i*VV;
    float val[4];
    float lmax = -1e30f; int lidx = 0;
    #pragma unroll
    for (int r=0;r<4;r++){
        int v = t + 256*r;
        if (v < VV){
            float x = S[v];
            val[r] = x;
            if (x > lmax){ lmax = x; lidx = v; }
        } else val[r] = -1e30f;
    }
    __shared__ float smax[256]; __shared__ int sidx[256];
    smax[t]=lmax; sidx[t]=lidx;
    __syncthreads();
    for (int st=128; st>0; st>>=1){
        if (t < st){
            float o = smax[t+st]; int oi = sidx[t+st];
            if (o > smax[t] || (o == smax[t] && oi < sidx[t])){ smax[t]=o; sidx[t]=oi; }
        }
        __syncthreads();
    }
    float m = smax[0]; int am = sidx[0];
    __syncthreads();
    float se = 0.f;
    #pragma unroll
    for (int r=0;r<4;r++){
        int v = t + 256*r;
        if (v < VV) se += expf(val[r] - m);
    }
    __shared__ float ssum[256];
    ssum[t]=se;
    __syncthreads();
    for (int st=128; st>0; st>>=1){
        if (t < st) ssum[t]+=ssum[t+st];
        __syncthreads();
    }
    if (t==0){
        float lse = m + logf(ssum[0]);
        int tg = target[i];
        float ce = lse - S[tg];
        float msk = (direction[i]==1) ? 1.f : 0.f;
        atomicAdd(&g_red[0], ce*msk);
        atomicAdd(&g_red[1], (am==tg) ? msk : 0.f);
        atomicAdd(&g_red[2], msk);
    }
}

__global__ void k_final(float* out)
{
    out[0] = g_red[0] / (float)BB;
    out[1] = g_red[3] / (float)BB;
    out[2] = g_red[1] / g_red[2];
    out[3] = g_red[4] / (float)NSTOP;
}

// ---------------- host launch ----------------
extern "C" void kernel_launch(void* const* d_in, const int* in_sizes, int n_in,
                              void* d_out, int out_size)
{
    const float* node_rep = (const float*)d_in[0];
    const int*   clique   = (const int*)  d_in[1];
    const int*   rclique  = (const int*)  d_in[2];
    const int*   nei_h    = (const int*)  d_in[3];
    const int*   nei_o    = (const int*)  d_in[4];
    const int*   rnei     = (const int*)  d_in[5];
    const int*   dir      = (const int*)  d_in[6];
    const int*   ptgt     = (const int*)  d_in[7];
    const float* Wz  = (const float*)d_in[8];
    const float* Wzb = (const float*)d_in[9];
    const float* Wr  = (const float*)d_in[10];
    const float* Wrb = (const float*)d_in[11];
    const float* Ur  = (const float*)d_in[12];
    const float* Wh  = (const float*)d_in[13];
    const float* Whb = (const float*)d_in[14];
    const float* Ww  = (const float*)d_in[15];
    const float* Wwb = (const float*)d_in[16];
    const float* Uw  = (const float*)d_in[17];
    const float* Ub  = (const float*)d_in[18];
    const float* Wo  = (const float*)d_in[19];
    const float* Wob = (const float*)d_in[20];
    const float* Us  = (const float*)d_in[21];
    const float* Usb = (const float*)d_in[22];

    float *tb, *tbU, *nZ, *nR, *nH, *stopA, *predH, *predS, *score, *red;
    unsigned* bar;
    cudaGetSymbolAddress((void**)&tb,    g_table);
    cudaGetSymbolAddress((void**)&tbU,   g_tableU);
    cudaGetSymbolAddress((void**)&nZ,    g_nodeZ);
    cudaGetSymbolAddress((void**)&nR,    g_nodeR);
    cudaGetSymbolAddress((void**)&nH,    g_nodeH);
    cudaGetSymbolAddress((void**)&stopA, g_stopA);
    cudaGetSymbolAddress((void**)&predH, g_predH);
    cudaGetSymbolAddress((void**)&predS, g_predS);
    cudaGetSymbolAddress((void**)&score, g_score);
    cudaGetSymbolAddress((void**)&red,   g_red);
    cudaGetSymbolAddress((void**)&bar,   g_bar);

    static int attr_set = 0;
    if (!attr_set){
        cudaFuncSetAttribute(k_scan, cudaFuncAttributeMaxDynamicSharedMemorySize, SMEM_SCAN);
        cudaFuncSetAttribute(tgemm<3,false,true>,  cudaFuncAttributeMaxDynamicSharedMemorySize, SMEM_TG);
        cudaFuncSetAttribute(tgemm<2,false,false>, cudaFuncAttributeMaxDynamicSharedMemorySize, SMEM_TG);
        cudaFuncSetAttribute(tgemm<1,false,false>, cudaFuncAttributeMaxDynamicSharedMemorySize, SMEM_TG);
        cudaFuncSetAttribute(tgemm<0,true,false>,  cudaFuncAttributeMaxDynamicSharedMemorySize, SMEM_TG);
        attr_set = 1;
    }

    cudaMemsetAsync(tb,   0, sizeof(float)*(size_t)NMSG*HH);
    cudaMemsetAsync(tbU,  0, sizeof(float)*(size_t)NMSG*HH);
    cudaMemsetAsync(score,0, sizeof(float)*NSTOP);
    cudaMemsetAsync(red,  0, sizeof(float)*8);
    cudaMemsetAsync(bar,  0, sizeof(unsigned));

    // x features + node-level projections (tf32)
    k_xfeat<<<BT+BB, 256>>>(node_rep, clique, rclique);

    dim3 gN(4, (BB*N_AT)/128, 3);
    tgemm<3,false,true><<<gN, 256, SMEM_TG>>>(node_rep, HH, Wz, HH, nullptr, nZ, HH,
                                              HH, HH, nullptr, Wr, Wh, nR, nH);
    k_xproj<<<BT, 256>>>(clique, Wzb, Wrb, Whb);

    // sequential scan: persistent kernel, tf32 mma + smem-resident weights
    const float* Wzh = Wz + (size_t)HH*HH;
    const float* Whh = Wh + (size_t)HH*HH;
    k_scan<<<NBLK, 256, SMEM_SCAN>>>(nei_h, Wzh, Whh, Ur);

    // stop head (tf32, fused relu+dot epilogue)
    k_oall<<<dim3(NSTOP,2), 256>>>(nei_o, rnei);
    tgemm<2,false,false><<<dim3(4, NSTOP/128), 256, SMEM_TG>>>(stopA, H2, Uw, HH, Ub,
                                                               nullptr, 0, HH, H2, Us,
                                                               nullptr, nullptr, nullptr, nullptr);
    k_stoploss<<<NSTOP/256, 256>>>(dir, Usb);

    // pred head (tf32)
    tgemm<1,false,false><<<dim3(4, BT/128), 256, SMEM_TG>>>(tb + HH, HH, Ww, HH, Wwb,
                                                            predH, HH, HH, HH, nullptr,
                                                            nullptr, nullptr, nullptr, nullptr);
    tgemm<0,true,false><<<dim3(7, BT/128), 256, SMEM_TG>>>(predH, HH, Wo, VV, Wob,
                                                           predS, VV, VV, HH, nullptr,
                                                           nullptr, nullptr, nullptr, nullptr);
    k_ce<<<BT, 256>>>(dir, ptgt);

    k_final<<<1,1>>>((float*)d_out);
}

// round 10
// speedup vs baseline: 1.0357x; 1.0357x over previous
#include <cuda_runtime.h>
#include <cuda_bf16.h>
#include <math.h>
#include <stdint.h>

#define BB 512
#define TT 64
#define HH 512
#define VV 780
#define N_AT 40
#define KC 4
#define MAX_NB 8
#define NMSG (BB*TT+1)
#define BT (BB*TT)
#define NSTOP (BT+BB)
#define H2 (2*HH)
#define NBLK 128

// k_scan smem: Wz+Wh resident [512][32] + 4-stage ring (stage = 18432 B)
#define RING_STAGE_B 18432
#define SMEM_SCAN (2*512*32*4 + 4*RING_STAGE_B)   // 204800 B

// tgemm: 3-stage ring of (A[128][36] + B[32][132]) fp32 tiles
#define TG_ABUF (128*36)
#define TG_BBUF (32*132)
#define TG_STAGE (TG_ABUF + TG_BBUF)
#define SMEM_TG (3*TG_STAGE*4)

// ---------------- device scratch ----------------
__device__ float g_table [NMSG*HH];
__device__ float g_tableU[NMSG*HH];
__device__ float g_nodeZ [BB*N_AT*HH];
__device__ float g_nodeR [BB*N_AT*HH];
__device__ float g_nodeH [BB*N_AT*HH];
__device__ float g_xall  [BT*HH];
__device__ float g_rootx [BB*HH];
__device__ float g_Xz    [BT*HH];
__device__ float g_Xr    [BT*HH];
__device__ float g_Xh    [BT*HH];
__device__ float g_sumh  [BB*HH];
__device__ float g_sumg  [BB*HH];
__device__ float g_stopA [NSTOP*H2];
__device__ float g_predH [BT*HH];
__device__ float g_predS [BT*VV];
__device__ float g_score [NSTOP];
__device__ float g_red   [8];
__device__ unsigned g_bar;

__device__ __forceinline__ float sigf(float x){ return 1.f/(1.f+expf(-x)); }

__device__ __forceinline__ void cp_async16(uint32_t dst, const void* src){
    asm volatile("cp.async.cg.shared.global [%0], [%1], 16;\n" :: "r"(dst), "l"(src));
}
__device__ __forceinline__ void cp_async16z(uint32_t dst, const void* src, int bytes){
    asm volatile("cp.async.cg.shared.global [%0], [%1], 16, %2;\n" :: "r"(dst), "l"(src), "r"(bytes));
}
__device__ __forceinline__ void cp_commit(){ asm volatile("cp.async.commit_group;\n"); }
template<int N> __device__ __forceinline__ void cp_wait(){ asm volatile("cp.async.wait_group %0;\n" :: "n"(N)); }

__device__ __forceinline__ void mma_tf32(float* d, const uint32_t* a, const uint32_t* b){
    asm volatile(
        "mma.sync.aligned.m16n8k8.row.col.f32.tf32.tf32.f32 "
        "{%0,%1,%2,%3},{%4,%5,%6,%7},{%8,%9},{%0,%1,%2,%3};\n"
        : "+f"(d[0]), "+f"(d[1]), "+f"(d[2]), "+f"(d[3])
        : "r"(a[0]), "r"(a[1]), "r"(a[2]), "r"(a[3]), "r"(b[0]), "r"(b[1]));
}

// ---------------- x features ----------------
__global__ void k_xfeat(const float* __restrict__ node_rep,
                        const int* __restrict__ cidx,
                        const int* __restrict__ rcidx)
{
    int i = blockIdx.x; int c = threadIdx.x;
    if (i < BT) {
        int b = i / TT;
        const int* ci = cidx + (size_t)i*KC;
        float s0=0.f, s1=0.f;
        #pragma unroll
        for (int k=0;k<KC;k++){
            const float* nr = node_rep + ((size_t)b*N_AT + ci[k])*HH;
            s0 += nr[c]; s1 += nr[c+256];
        }
        g_xall[(size_t)i*HH + c]       = s0;
        g_xall[(size_t)i*HH + c + 256] = s1;
    } else {
        int b = i - BT;
        const int* ci = rcidx + (size_t)b*KC;
        float s0=0.f, s1=0.f;
        #pragma unroll
        for (int k=0;k<KC;k++){
            const float* nr = node_rep + ((size_t)b*N_AT + ci[k])*HH;
            s0 += nr[c]; s1 += nr[c+256];
        }
        g_rootx[b*HH + c]       = s0;
        g_rootx[b*HH + c + 256] = s1;
    }
}

// ---------------- gather node projections into per-(b,t) X arrays ----------------
__global__ void k_xproj(const int* __restrict__ cidx,
                        const float* __restrict__ bz,
                        const float* __restrict__ br,
                        const float* __restrict__ bh)
{
    int i = blockIdx.x;
    int b = i / TT;
    const int* ci = cidx + (size_t)i*KC;
    int r0 = b*N_AT;
    #pragma unroll
    for (int cc=0; cc<2; cc++){
        int c = threadIdx.x + cc*256;
        float sz = bz[c], sr = br[c], sh = bh[c];
        #pragma unroll
        for (int k=0;k<KC;k++){
            size_t row = (size_t)(r0 + ci[k])*HH + c;
            sz += g_nodeZ[row];
            sr += g_nodeR[row];
            sh += g_nodeH[row];
        }
        g_Xz[(size_t)i*HH + c] = sz;
        g_Xr[(size_t)i*HH + c] = sr;
        g_Xh[(size_t)i*HH + c] = sh;
    }
}

// ---------------- tf32 tensor-core GEMM ----------------
template<int EPI, bool NG, bool ZSEL>
__global__ void __launch_bounds__(256)
tgemm(const float* __restrict__ A, int lda,
      const float* __restrict__ Bm0, int ldb,
      const float* __restrict__ bias,
      float* __restrict__ C0, int ldc,
      int N, int K,
      const float* __restrict__ us,
      const float* Bm1, const float* Bm2,
      float* C1, float* C2)
{
    extern __shared__ float dynsm[];
    const int tid  = threadIdx.x;
    const int warp = tid >> 5, lane = tid & 31;
    const int wm = warp & 3, wn = warp >> 2;
    const int gid = lane >> 2, tig = lane & 3;
    const int by = blockIdx.y, bx = blockIdx.x;
    const int rowb = by*128, colb = bx*128;

    const float* Bm = Bm0;
    float* C = C0;
    if (ZSEL){
        if (blockIdx.z == 1){ Bm = Bm1; C = C1; }
        else if (blockIdx.z == 2){ Bm = Bm2; C = C2; }
    }

    const int aq0 = tid;
    const int bq0 = tid;

    uint32_t smem_base = (uint32_t)__cvta_generic_to_shared(dynsm);

    float acc[2][8][4];
    #pragma unroll
    for (int mt=0;mt<2;mt++)
        #pragma unroll
        for (int nt=0;nt<8;nt++)
            #pragma unroll
            for (int i=0;i<4;i++) acc[mt][nt][i]=0.f;

    const int nk = K >> 5;

    auto issue = [&](int kt, int stage){
        uint32_t sa = smem_base + stage*TG_STAGE*4;
        uint32_t sb = sa + TG_ABUF*4;
        #pragma unroll
        for (int i=0;i<4;i++){
            int q = aq0 + 256*i;
            int r = q >> 3, k4 = (q & 7)*4;
            cp_async16(sa + (r*36 + k4)*4, A + (size_t)(rowb + r)*lda + kt*32 + k4);
        }
        #pragma unroll
        for (int i=0;i<4;i++){
            int q = bq0 + 256*i;
            int kr = q >> 5, n4 = (q & 31)*4;
            uint32_t dst = sb + (kr*132 + n4)*4;
            if (NG){
                int col = colb + n4;
                int bytes = (col + 3 < N) ? 16 : ((col < N) ? (N - col)*4 : 0);
                const float* src = Bm + (size_t)(kt*32 + kr)*ldb + (bytes ? col : 0);
                cp_async16z(dst, src, bytes);
            } else {
                cp_async16(dst, Bm + (size_t)(kt*32 + kr)*ldb + colb + n4);
            }
        }
        cp_commit();
    };

    issue(0, 0);
    if (nk > 1) issue(1, 1);

    for (int it=0; it<nk; it++){
        if (it+2 < nk) issue(it+2, (it+2)%3);
        if (it+1 < nk) cp_wait<1>(); else cp_wait<0>();
        __syncthreads();

        const uint32_t* As = (const uint32_t*)(dynsm + (it%3)*TG_STAGE);
        const uint32_t* Bs = (const uint32_t*)(dynsm + (it%3)*TG_STAGE + TG_ABUF);

        #pragma unroll
        for (int ks=0; ks<4; ks++){
            uint32_t af[2][4];
            #pragma unroll
            for (int mt=0; mt<2; mt++){
                int r = wm*32 + mt*16 + gid;
                af[mt][0] = As[r*36 + ks*8 + tig];
                af[mt][1] = As[(r+8)*36 + ks*8 + tig];
                af[mt][2] = As[r*36 + ks*8 + tig + 4];
                af[mt][3] = As[(r+8)*36 + ks*8 + tig + 4];
            }
            uint32_t bf[8][2];
            #pragma unroll
            for (int nt=0; nt<8; nt++){
                int n = wn*64 + nt*8 + gid;
                bf[nt][0] = Bs[(ks*8 + tig)*132 + n];
                bf[nt][1] = Bs[(ks*8 + tig + 4)*132 + n];
            }
            #pragma unroll
            for (int mt=0; mt<2; mt++)
                #pragma unroll
                for (int nt=0; nt<8; nt++)
                    mma_tf32(acc[mt][nt], af[mt], bf[nt]);
        }
        __syncthreads();
    }

    if (EPI == 2){
        #pragma unroll
        for (int mt=0; mt<2; mt++){
            float s0 = 0.f, s1 = 0.f;
            #pragma unroll
            for (int nt=0; nt<8; nt++){
                int col = colb + wn*64 + nt*8 + 2*tig;
                float b0 = bias[col], b1 = bias[col+1];
                float u0 = us[col],  u1 = us[col+1];
                float v;
                v = acc[mt][nt][0] + b0; s0 += (v>0.f? v:0.f)*u0;
                v = acc[mt][nt][1] + b1; s0 += (v>0.f? v:0.f)*u1;
                v = acc[mt][nt][2] + b0; s1 += (v>0.f? v:0.f)*u0;
                v = acc[mt][nt][3] + b1; s1 += (v>0.f? v:0.f)*u1;
            }
            s0 += __shfl_xor_sync(0xffffffffu, s0, 1);
            s0 += __shfl_xor_sync(0xffffffffu, s0, 2);
            s1 += __shfl_xor_sync(0xffffffffu, s1, 1);
            s1 += __shfl_xor_sync(0xffffffffu, s1, 2);
            if (tig == 0){
                int row = rowb + wm*32 + mt*16 + gid;
                atomicAdd(&g_score[row], s0);
                atomicAdd(&g_score[row+8], s1);
            }
        }
    } else {
        #pragma unroll
        for (int mt=0; mt<2; mt++){
            #pragma unroll
            for (int nt=0; nt<8; nt++){
                int col = colb + wn*64 + nt*8 + 2*tig;
                int row = rowb + wm*32 + mt*16 + gid;
                #pragma unroll
                for (int i=0; i<4; i++){
                    int cc = col + (i & 1);
                    int rr = row + ((i >> 1) ? 8 : 0);
                    if (!NG || cc < N){
                        float v = acc[mt][nt][i];
                        if (EPI != 3) v += bias[cc];
                        if (EPI == 1) v = v > 0.f ? v : 0.f;
                        C[(size_t)rr*ldc + cc] = v;
                    }
                }
            }
        }
    }
}

// ---------------- persistent scan kernel ----------------
// Grid barrier, cooperative-groups style: block sync (drains & orders the
// block's stores at CTA scope), then ONE thread fences (cumulative release of
// the observed writes to GPU scope) + bumps the counter + tight-spins.
__device__ __forceinline__ void gsync(int& epoch)
{
    __syncthreads();
    if (threadIdx.x == 0){
        __threadfence();
        atomicAdd(&g_bar, 1u);
        unsigned tgt = (unsigned)epoch * NBLK;
        while (*((volatile unsigned*)&g_bar) < tgt) { }
    }
    epoch++;
    __syncthreads();
}

__global__ void __launch_bounds__(256, 1)
k_scan(const int* __restrict__ nei_h,
       const float* __restrict__ Wzh,
       const float* __restrict__ Whh,
       const float* __restrict__ Ur)
{
    extern __shared__ float smem[];
    float* Wz_s = smem;                    // [512][32] swizzled
    float* Wh_s = Wz_s + 512*32;
    float* ringf = Wh_s + 512*32;          // 4 stages x 4608 floats

    const int tid = threadIdx.x;
    const int blk = blockIdx.x;
    const int rt = blk >> 4, ct = blk & 15;     // 8 row tiles x 16 col tiles
    const int r0 = rt*64, c0 = ct*32;
    const int warp = tid >> 5, lane = tid & 31;
    const int wm = warp & 3, wn = warp >> 2;    // warp tile 16x16
    const int gid = lane >> 2, tig = lane & 3;
    const int id4a = tid*2, id4b = tid*2+1;
    const int sra = id4a >> 3, ska = (id4a & 7)*4;
    const int srb = id4b >> 3, skb = (id4b & 7)*4;
    const int ur_r = tid >> 3, ur_c = (tid & 7)*4;   // Ur chunk staging [32][40]

    const uint32_t ring_u = (uint32_t)__cvta_generic_to_shared(ringf);

    for (int idx = tid; idx < 512*32; idx += 256){
        int k = idx >> 5; int cc = idx & 31;
        int sw = cc ^ ((k & 3) << 3);
        Wz_s[k*32 + sw] = Wzh[(size_t)k*HH + c0 + cc];
        Wh_s[k*32 + sw] = Whh[(size_t)k*HH + c0 + cc];
    }
    __syncthreads();

    const uint32_t* Wz32 = (const uint32_t*)Wz_s;
    const uint32_t* Wh32 = (const uint32_t*)Wh_s;

    int epoch = 1;

    for (int t = 0; t < TT; t++){
        // ---- phase A: gather sum_h, sum_g ----
        #pragma unroll
        for (int rb=0; rb<4; rb++){
            int b = blk*4 + rb;
            const int* idx = nei_h + ((size_t)b*TT + t)*MAX_NB;
            int ii[8];
            #pragma unroll
            for (int n=0;n<8;n++) ii[n] = idx[n];
            #pragma unroll
            for (int cc=0; cc<2; cc++){
                int ch = tid + cc*256;
                float xr = g_Xr[((size_t)b*TT + t)*HH + ch];
                float ah=0.f, ag=0.f;
                #pragma unroll
                for (int n=0;n<8;n++){
                    size_t base = (size_t)ii[n]*HH + ch;
                    float hv = __ldcg(&g_table[base]);
                    float uv = __ldcg(&g_tableU[base]);
                    ah += hv;
                    ag += hv * sigf(xr + uv);
                }
                g_sumh[b*HH+ch] = ah;
                g_sumg[b*HH+ch] = ag;
            }
        }
        gsync(epoch);

        // ---- phase B: dual tf32 GEMM (4-stage cp.async ring) + GRU epilogue ----
        {
            float accz[2][4], acch[2][4];
            #pragma unroll
            for (int nt=0;nt<2;nt++)
                #pragma unroll
                for (int i=0;i<4;i++){ accz[nt][i]=0.f; acch[nt][i]=0.f; }

            auto issueB = [&](int chk){
                uint32_t sa = ring_u + (chk & 3)*RING_STAGE_B;
                cp_async16(sa + (sra*36+ska)*4, &g_sumh[(size_t)(r0+sra)*HH + chk*32 + ska]);
                cp_async16(sa + (srb*36+skb)*4, &g_sumh[(size_t)(r0+srb)*HH + chk*32 + skb]);
                cp_async16(sa + 9216 + (sra*36+ska)*4, &g_sumg[(size_t)(r0+sra)*HH + chk*32 + ska]);
                cp_async16(sa + 9216 + (srb*36+skb)*4, &g_sumg[(size_t)(r0+srb)*HH + chk*32 + skb]);
                cp_commit();
            };
            issueB(0); issueB(1); issueB(2);

            for (int chk=0; chk<16; chk++){
                if (chk < 14) cp_wait<2>(); else if (chk == 14) cp_wait<1>(); else cp_wait<0>();
                __syncthreads();
                if (chk+3 < 16) issueB(chk+3);

                const uint32_t* Ah = (const uint32_t*)(ringf + (chk & 3)*4608);
                const uint32_t* Ag = Ah + 2304;

                #pragma unroll
                for (int ks=0; ks<4; ks++){
                    int rb0 = wm*16 + gid;
                    uint32_t ah[4], ag[4];
                    ah[0]=Ah[rb0*36 + ks*8 + tig];     ah[1]=Ah[(rb0+8)*36 + ks*8 + tig];
                    ah[2]=Ah[rb0*36 + ks*8 + tig + 4]; ah[3]=Ah[(rb0+8)*36 + ks*8 + tig + 4];
                    ag[0]=Ag[rb0*36 + ks*8 + tig];     ag[1]=Ag[(rb0+8)*36 + ks*8 + tig];
                    ag[2]=Ag[rb0*36 + ks*8 + tig + 4]; ag[3]=Ag[(rb0+8)*36 + ks*8 + tig + 4];
                    int kg = chk*32 + ks*8;
                    #pragma unroll
                    for (int nt=0; nt<2; nt++){
                        int n = wn*16 + nt*8 + gid;
                        int nsw = n ^ (tig << 3);
                        uint32_t bz[2], bh[2];
                        bz[0] = Wz32[(kg+tig)*32 + nsw];
                        bz[1] = Wz32[(kg+tig+4)*32 + nsw];
                        bh[0] = Wh32[(kg+tig)*32 + nsw];
                        bh[1] = Wh32[(kg+tig+4)*32 + nsw];
                        mma_tf32(accz[nt], ah, bz);
                        mma_tf32(acch[nt], ag, bh);
                    }
                }
            }

            #pragma unroll
            for (int nt=0; nt<2; nt++){
                #pragma unroll
                for (int half=0; half<2; half++){
                    int b   = r0 + wm*16 + gid + half*8;
                    int col = c0 + wn*16 + nt*8 + tig*2;
                    size_t xi = ((size_t)b*TT + t)*HH + col;
                    float2 xz = *(const float2*)&g_Xz[xi];
                    float2 xh = *(const float2*)&g_Xh[xi];
                    float2 sh = __ldcg((const float2*)&g_sumh[(size_t)b*HH + col]);
                    float z0 = sigf(xz.x + accz[nt][half*2+0]);
                    float z1 = sigf(xz.y + accz[nt][half*2+1]);
                    float p0 = tanhf(xh.x + acch[nt][half*2+0]);
                    float p1 = tanhf(xh.y + acch[nt][half*2+1]);
                    float2 out;
                    out.x = (1.f - z0)*sh.x + z0*p0;
                    out.y = (1.f - z1)*sh.y + z1*p1;
                    *(float2*)&g_table[((size_t)b*TT + t + 1)*HH + col] = out;
                }
            }
        }
        gsync(epoch);

        if (t == TT-1) break;

        // ---- phase C: tableU(new rows) = new_h @ Ur (4-stage ring, Ur streamed) ----
        {
            float accu[2][4];
            #pragma unroll
            for (int nt=0;nt<2;nt++)
                #pragma unroll
                for (int i=0;i<4;i++) accu[nt][i]=0.f;

            auto issueC = [&](int chk){
                uint32_t sa = ring_u + (chk & 3)*RING_STAGE_B;
                cp_async16(sa + (sra*36+ska)*4, &g_table[((size_t)(r0+sra)*TT + t + 1)*HH + chk*32 + ska]);
                cp_async16(sa + (srb*36+skb)*4, &g_table[((size_t)(r0+srb)*TT + t + 1)*HH + chk*32 + skb]);
                cp_async16(sa + 9216 + (ur_r*40 + ur_c)*4, &Ur[(size_t)(chk*32 + ur_r)*HH + c0 + ur_c]);
                cp_commit();
            };
            issueC(0); issueC(1); issueC(2);

            for (int chk=0; chk<16; chk++){
                if (chk < 14) cp_wait<2>(); else if (chk == 14) cp_wait<1>(); else cp_wait<0>();
                __syncthreads();
                if (chk+3 < 16) issueC(chk+3);

                const uint32_t* Ah = (const uint32_t*)(ringf + (chk & 3)*4608);
                const uint32_t* Uc = Ah + 2304;   // [32][40]

                #pragma unroll
                for (int ks=0; ks<4; ks++){
                    int rb0 = wm*16 + gid;
                    uint32_t ah[4];
                    ah[0]=Ah[rb0*36 + ks*8 + tig];     ah[1]=Ah[(rb0+8)*36 + ks*8 + tig];
                    ah[2]=Ah[rb0*36 + ks*8 + tig + 4]; ah[3]=Ah[(rb0+8)*36 + ks*8 + tig + 4];
                    #pragma unroll
                    for (int nt=0; nt<2; nt++){
                        int n = wn*16 + nt*8 + gid;
                        uint32_t bu[2];
                        bu[0] = Uc[(ks*8 + tig)*40 + n];
                        bu[1] = Uc[(ks*8 + tig + 4)*40 + n];
                        mma_tf32(accu[nt], ah, bu);
                    }
                }
            }

            #pragma unroll
            for (int nt=0; nt<2; nt++){
                #pragma unroll
                for (int half=0; half<2; half++){
                    int b   = r0 + wm*16 + gid + half*8;
                    int col = c0 + wn*16 + nt*8 + tig*2;
                    float2 out;
                    out.x = accu[nt][half*2+0];
                    out.y = accu[nt][half*2+1];
                    *(float2*)&g_tableU[((size_t)b*TT + t + 1)*HH + col] = out;
                }
            }
        }
        gsync(epoch);
    }
}

// ---------------- deferred o gather + concat into stopA ----------------
__global__ void k_oall(const int* __restrict__ nei_o, const int* __restrict__ root_nei)
{
    int i = blockIdx.x;
    int c = blockIdx.y*256 + threadIdx.x;
    if (i < BT) {
        int tt = i % TT;
        float xv = g_xall[(size_t)i*HH + c];
        const int* idx = nei_o + (size_t)i*MAX_NB;
        float o = 0.f;
        #pragma unroll
        for (int n=0;n<MAX_NB;n++){
            int id = idx[n];
            if (id > 0 && ((id-1) % TT) < tt) o += g_table[(size_t)id*HH + c];
        }
        g_stopA[(size_t)i*H2 + c]      = xv;
        g_stopA[(size_t)i*H2 + HH + c] = o;
    } else {
        int b = i - BT;
        float xv = g_rootx[b*HH + c];
        const int* idx = root_nei + (size_t)b*MAX_NB;
        float o = 0.f;
        #pragma unroll
        for (int n=0;n<MAX_NB;n++) o += g_table[(size_t)idx[n]*HH + c];
        g_stopA[(size_t)i*H2 + c]      = xv;
        g_stopA[(size_t)i*H2 + HH + c] = o;
    }
}

// ---------------- stop loss / acc ----------------
__global__ void k_stoploss(const int* __restrict__ direction, const float* __restrict__ usb)
{
    int i = blockIdx.x*256 + threadIdx.x;
    float li = 0.f, ci = 0.f;
    if (i < NSTOP){
        float s = g_score[i] + usb[0];
        float tgt = (i < BT) ? (float)direction[i] : 0.f;
        float sp = (s > 0.f) ? (s + log1pf(expf(-s))) : log1pf(expf(s));
        li = sp - s*tgt;
        float pred = (s >= 0.f) ? 1.f : 0.f;
        ci = (pred == tgt) ? 1.f : 0.f;
    }
    __shared__ float rl[256], rc[256];
    rl[threadIdx.x]=li; rc[threadIdx.x]=ci;
    __syncthreads();
    for (int st=128; st>0; st>>=1){
        if (threadIdx.x < st){ rl[threadIdx.x]+=rl[threadIdx.x+st]; rc[threadIdx.x]+=rc[threadIdx.x+st]; }
        __syncthreads();
    }
    if (threadIdx.x==0){
        atomicAdd(&g_red[3], rl[0]);
        atomicAdd(&g_red[4], rc[0]);
    }
}

// ---------------- pred head CE / acc ----------------
__global__ void k_ce(const int* __restrict__ direction, const int* __restrict__ target)
{
    int i = blockIdx.x;
    int t = threadIdx.x;
    const float* S = g_predS + (size_t)i*VV;
    float val[4];
    float lmax = -1e30f; int lidx = 0;
    #pragma unroll
    for (int r=0;r<4;r++){
        int v = t + 256*r;
        if (v < VV){
            float x = S[v];
            val[r] = x;
            if (x > lmax){ lmax = x; lidx = v; }
        } else val[r] = -1e30f;
    }
    __shared__ float smax[256]; __shared__ int sidx[256];
    smax[t]=lmax; sidx[t]=lidx;
    __syncthreads();
    for (int st=128; st>0; st>>=1){
        if (t < st){
            float o = smax[t+st]; int oi = sidx[t+st];
            if (o > smax[t] || (o == smax[t] && oi < sidx[t])){ smax[t]=o; sidx[t]=oi; }
        }
        __syncthreads();
    }
    float m = smax[0]; int am = sidx[0];
    __syncthreads();
    float se = 0.f;
    #pragma unroll
    for (int r=0;r<4;r++){
        int v = t + 256*r;
        if (v < VV) se += expf(val[r] - m);
    }
    __shared__ float ssum[256];
    ssum[t]=se;
    __syncthreads();
    for (int st=128; st>0; st>>=1){
        if (t < st) ssum[t]+=ssum[t+st];
        __syncthreads();
    }
    if (t==0){
        float lse = m + logf(ssum[0]);
        int tg = target[i];
        float ce = lse - S[tg];
        float msk = (direction[i]==1) ? 1.f : 0.f;
        atomicAdd(&g_red[0], ce*msk);
        atomicAdd(&g_red[1], (am==tg) ? msk : 0.f);
        atomicAdd(&g_red[2], msk);
    }
}

__global__ void k_final(float* out)
{
    out[0] = g_red[0] / (float)BB;
    out[1] = g_red[3] / (float)BB;
    out[2] = g_red[1] / g_red[2];
    out[3] = g_red[4] / (float)NSTOP;
}

// ---------------- host launch ----------------
extern "C" void kernel_launch(void* const* d_in, const int* in_sizes, int n_in,
                              void* d_out, int out_size)
{
    const float* node_rep = (const float*)d_in[0];
    const int*   clique   = (const int*)  d_in[1];
    const int*   rclique  = (const int*)  d_in[2];
    const int*   nei_h    = (const int*)  d_in[3];
    const int*   nei_o    = (const int*)  d_in[4];
    const int*   rnei     = (const int*)  d_in[5];
    const int*   dir      = (const int*)  d_in[6];
    const int*   ptgt     = (const int*)  d_in[7];
    const float* Wz  = (const float*)d_in[8];
    const float* Wzb = (const float*)d_in[9];
    const float* Wr  = (const float*)d_in[10];
    const float* Wrb = (const float*)d_in[11];
    const float* Ur  = (const float*)d_in[12];
    const float* Wh  = (const float*)d_in[13];
    const float* Whb = (const float*)d_in[14];
    const float* Ww  = (const float*)d_in[15];
    const float* Wwb = (const float*)d_in[16];
    const float* Uw  = (const float*)d_in[17];
    const float* Ub  = (const float*)d_in[18];
    const float* Wo  = (const float*)d_in[19];
    const float* Wob = (const float*)d_in[20];
    const float* Us  = (const float*)d_in[21];
    const float* Usb = (const float*)d_in[22];

    float *tb, *tbU, *nZ, *nR, *nH, *stopA, *predH, *predS, *score, *red;
    unsigned* bar;
    cudaGetSymbolAddress((void**)&tb,    g_table);
    cudaGetSymbolAddress((void**)&tbU,   g_tableU);
    cudaGetSymbolAddress((void**)&nZ,    g_nodeZ);
    cudaGetSymbolAddress((void**)&nR,    g_nodeR);
    cudaGetSymbolAddress((void**)&nH,    g_nodeH);
    cudaGetSymbolAddress((void**)&stopA, g_stopA);
    cudaGetSymbolAddress((void**)&predH, g_predH);
    cudaGetSymbolAddress((void**)&predS, g_predS);
    cudaGetSymbolAddress((void**)&score, g_score);
    cudaGetSymbolAddress((void**)&red,   g_red);
    cudaGetSymbolAddress((void**)&bar,   g_bar);

    static int attr_set = 0;
    if (!attr_set){
        cudaFuncSetAttribute(k_scan, cudaFuncAttributeMaxDynamicSharedMemorySize, SMEM_SCAN);
        cudaFuncSetAttribute(tgemm<3,false,true>,  cudaFuncAttributeMaxDynamicSharedMemorySize, SMEM_TG);
        cudaFuncSetAttribute(tgemm<2,false,false>, cudaFuncAttributeMaxDynamicSharedMemorySize, SMEM_TG);
        cudaFuncSetAttribute(tgemm<1,false,false>, cudaFuncAttributeMaxDynamicSharedMemorySize, SMEM_TG);
        cudaFuncSetAttribute(tgemm<0,true,false>,  cudaFuncAttributeMaxDynamicSharedMemorySize, SMEM_TG);
        attr_set = 1;
    }

    cudaMemsetAsync(tb,   0, sizeof(float)*(size_t)NMSG*HH);
    cudaMemsetAsync(tbU,  0, sizeof(float)*(size_t)NMSG*HH);
    cudaMemsetAsync(score,0, sizeof(float)*NSTOP);
    cudaMemsetAsync(red,  0, sizeof(float)*8);
    cudaMemsetAsync(bar,  0, sizeof(unsigned));

    // x features + node-level projections (tf32)
    k_xfeat<<<BT+BB, 256>>>(node_rep, clique, rclique);

    dim3 gN(4, (BB*N_AT)/128, 3);
    tgemm<3,false,true><<<gN, 256, SMEM_TG>>>(node_rep, HH, Wz, HH, nullptr, nZ, HH,
                                              HH, HH, nullptr, Wr, Wh, nR, nH);
    k_xproj<<<BT, 256>>>(clique, Wzb, Wrb, Whb);

    // sequential scan: persistent kernel, tf32 mma, cp.async rings
    const float* Wzh = Wz + (size_t)HH*HH;
    const float* Whh = Wh + (size_t)HH*HH;
    k_scan<<<NBLK, 256, SMEM_SCAN>>>(nei_h, Wzh, Whh, Ur);

    // stop head (tf32, fused relu+dot epilogue)
    k_oall<<<dim3(NSTOP,2), 256>>>(nei_o, rnei);
    tgemm<2,false,false><<<dim3(4, NSTOP/128), 256, SMEM_TG>>>(stopA, H2, Uw, HH, Ub,
                                                               nullptr, 0, HH, H2, Us,
                                                               nullptr, nullptr, nullptr, nullptr);
    k_stoploss<<<NSTOP/256, 256>>>(dir, Usb);

    // pred head (tf32)
    tgemm<1,false,false><<<dim3(4, BT/128), 256, SMEM_TG>>>(tb + HH, HH, Ww, HH, Wwb,
                                                            predH, HH, HH, HH, nullptr,
                                                            nullptr, nullptr, nullptr, nullptr);
    tgemm<0,true,false><<<dim3(7, BT/128), 256, SMEM_TG>>>(predH, HH, Wo, VV, Wob,
                                                           predS, VV, VV, HH, nullptr,
                                                           nullptr, nullptr, nullptr, nullptr);
    k_ce<<<BT, 256>>>(dir, ptgt);

    k_final<<<1,1>>>((float*)d_out);
}